// round 8
// baseline (speedup 1.0000x reference)
#include <cuda_runtime.h>

// B=128, N=1024. out[b,k] = a[b,j] - a[b,i], strict upper triangle (j>i),
// row-major pair order. Row i (len 1023-i) starts at off(i) = i*(2047-i)/2.
//
// Decomposition: one ROW-PAIR per TWO warps. Pair p = row p (len 1023-p) +
// row 1022-p (len p+1) = exactly 1024 outputs. Each warp-half h covers
// q-batches {h*32 + 64*u + lane}. Row index comes from the schedule (zero
// per-element index math). Loads are batched (predicated, back-to-back) for
// MLP ~6 with only ~24 value registers -> high occupancy.

constexpr int N_ELEM  = 1024;
constexpr int M_PAIRS = N_ELEM * (N_ELEM - 1) / 2;   // 523776
constexpr int THREADS = 256;                          // 8 warps -> 4 pairs/block
constexpr int PITCH   = N_ELEM + 4;                   // 16B-aligned copy pitch
constexpr int UL      = 4;                            // long-row batches per half
constexpr int US      = 2;                            // short-row batches per half

__device__ __forceinline__ int row_off(int i) {
    return (i * (2047 - i)) >> 1;                     // exact (product even)
}

struct RowCtx {
    const float* src;   // aligned smem source (shifted copy)
    float* dst;         // aligned global dest
    int n4;             // aligned float4 count
    float ai;
};

__device__ __forceinline__ RowCtx row_setup(int i, const float* __restrict__ sh,
                                            float* __restrict__ outb,
                                            int lane, bool peel) {
    const int start = row_off(i);
    const int len   = 1023 - i;
    const int end   = start + len;
    const float ai  = sh[i];                          // broadcast LDS

    const int astart = (start + 3) & ~3;
    const int aend   = end & ~3;

    if (peel) {
        // Head scalars (<=3 lanes)
        const int head_n = min(astart, end) - start;
        if (lane < head_n)
            outb[start + lane] = sh[i + 1 + lane] - ai;
        // Tail scalars (<=3 lanes)
        const int tstart = max(aend, astart);
        const int tail_n = end - tstart;
        if (lane < tail_n)
            outb[tstart + lane] = sh[i + 1 + (tstart - start) + lane] - ai;
    }

    int n4 = (aend - astart) >> 2;
    if (n4 < 0) n4 = 0;
    const int jbase = i + 1 + (astart - start);
    const int r     = jbase & 3;

    RowCtx c;
    c.src = sh + r * PITCH + (jbase - r);
    c.dst = outb + astart;
    c.n4  = n4;
    c.ai  = ai;
    return c;
}

__global__ __launch_bounds__(THREADS)
void relpos_kernel(const float* __restrict__ in, float* __restrict__ out) {
    // 4 shifted copies: sh[r*PITCH + m] = a[m + r]
    __shared__ float sh[4 * PITCH];

    const int b = blockIdx.y;
    const float* a = in + (size_t)b * N_ELEM;

    // Stage input + build shifted copies (one float4 per thread).
    {
        const float4 v = reinterpret_cast<const float4*>(a)[threadIdx.x];
        const int idx = threadIdx.x * 4;
        const float vv[4] = {v.x, v.y, v.z, v.w};
        #pragma unroll
        for (int e = 0; e < 4; e++) {
            const int x = idx + e;
            const float val = vv[e];
            #pragma unroll
            for (int r = 0; r < 4; r++) {
                const int m = x - r;
                if (m >= 0) sh[r * PITCH + m] = val;
            }
        }
    }
    __syncthreads();

    float* outb = out + (size_t)b * M_PAIRS;
    const int warp = threadIdx.x >> 5;
    const int lane = threadIdx.x & 31;

    const int gw = blockIdx.x * (THREADS / 32) + warp; // global warp 0..1023
    const int p  = gw >> 1;                            // pair id 0..511
    const int h  = gw & 1;                             // half id
    const int iS = 1022 - p;
    const bool hasS = (p < 511);
    const int qbase = h * 32 + lane;                   // this half's q offsets

    RowCtx L = row_setup(p, sh, outb, lane, h == 0);
    RowCtx S;
    S.n4 = 0; S.ai = 0.f; S.src = sh; S.dst = outb;
    if (hasS) S = row_setup(iS, sh, outb, lane, h == 0);

    // ---- Phase 1: all loads back-to-back (MLP ~6) ----
    float4 Lv[UL], Sv[US];
    #pragma unroll
    for (int u = 0; u < UL; u++) {
        const int q = qbase + 64 * u;
        if (q < L.n4)
            Lv[u] = *reinterpret_cast<const float4*>(L.src + (q << 2));
    }
    #pragma unroll
    for (int u = 0; u < US; u++) {
        const int q = qbase + 64 * u;
        if (q < S.n4)
            Sv[u] = *reinterpret_cast<const float4*>(S.src + (q << 2));
    }

    // ---- Phase 2: compute + store ----
    #pragma unroll
    for (int u = 0; u < UL; u++) {
        const int q = qbase + 64 * u;
        if (q < L.n4) {
            const float4 v = Lv[u];
            *reinterpret_cast<float4*>(L.dst + (q << 2)) =
                make_float4(v.x - L.ai, v.y - L.ai, v.z - L.ai, v.w - L.ai);
        }
    }
    #pragma unroll
    for (int u = 0; u < US; u++) {
        const int q = qbase + 64 * u;
        if (q < S.n4) {
            const float4 v = Sv[u];
            *reinterpret_cast<float4*>(S.dst + (q << 2)) =
                make_float4(v.x - S.ai, v.y - S.ai, v.z - S.ai, v.w - S.ai);
        }
    }
}

extern "C" void kernel_launch(void* const* d_in, const int* in_sizes, int n_in,
                              void* d_out, int out_size) {
    const float* in = (const float*)d_in[0];
    float* out = (float*)d_out;
    const int B = in_sizes[0] / N_ELEM;               // 128

    // 1024 global warps per batch / 8 warps per block = 128 x-blocks
    dim3 grid(128, B);                                 // (128, 128)
    relpos_kernel<<<grid, THREADS>>>(in, out);
}

// round 9
// speedup vs baseline: 1.3015x; 1.3015x over previous
#include <cuda_runtime.h>

// B=128, N=1024. out[b,k] = a[b,j] - a[b,i], strict upper triangle (j>i),
// row-major pair order. Row i (len 1023-i) starts at off(i) = i*(2047-i)/2.
//
// One ROW-PAIR per warp (pair p = row p + row 1022-p = exactly 1024 outputs);
// each warp processes TWO pairs (16 pairs/block, grid 32x128) to amortize the
// smem staging. Per pair, the 12 possible 32-float4 batches (8 long + 4 short)
// run as two pipelined groups of 6: loads batched back-to-back (MLP 6) with
// only 6 live float4 buffers -> ~46 regs, decent occupancy.

constexpr int N_ELEM  = 1024;
constexpr int M_PAIRS = N_ELEM * (N_ELEM - 1) / 2;   // 523776
constexpr int THREADS = 256;                          // 8 warps
constexpr int PAIRS_PER_BLOCK = 16;                   // 2 pairs per warp
constexpr int PITCH   = N_ELEM + 4;                   // 16B-aligned copy pitch

__device__ __forceinline__ int row_off(int i) {
    return (i * (2047 - i)) >> 1;                     // exact (product even)
}

struct RowCtx {
    const float* src;   // aligned smem source (shifted copy)
    float* dst;         // aligned global dest
    int n4;             // aligned float4 count
    float ai;
};

__device__ __forceinline__ RowCtx row_setup(int i, const float* __restrict__ sh,
                                            float* __restrict__ outb, int lane) {
    const int start = row_off(i);
    const int len   = 1023 - i;
    const int end   = start + len;
    const float ai  = sh[i];                          // broadcast LDS

    const int astart = (start + 3) & ~3;
    const int aend   = end & ~3;

    // Head scalars (<=3 lanes)
    const int head_n = min(astart, end) - start;
    if (lane < head_n)
        outb[start + lane] = sh[i + 1 + lane] - ai;
    // Tail scalars (<=3 lanes)
    const int tstart = max(aend, astart);
    const int tail_n = end - tstart;
    if (lane < tail_n)
        outb[tstart + lane] = sh[i + 1 + (tstart - start) + lane] - ai;

    int n4 = (aend - astart) >> 2;
    if (n4 < 0) n4 = 0;
    const int jbase = i + 1 + (astart - start);
    const int r     = jbase & 3;

    RowCtx c;
    c.src = sh + r * PITCH + (jbase - r);
    c.dst = outb + astart;
    c.n4  = n4;
    c.ai  = ai;
    return c;
}

// One group of up to NL long-batches + NS short-batches, loads first (MLP),
// then compute+store. uL0/uS0 are the starting batch indices.
template <int NL, int NS>
__device__ __forceinline__ void do_group(const RowCtx& L, const RowCtx& S,
                                         int lane, int uL0, int uS0) {
    float4 Lv[NL], Sv[NS];
    #pragma unroll
    for (int u = 0; u < NL; u++) {
        const int q = lane + 32 * (uL0 + u);
        if (q < L.n4)
            Lv[u] = *reinterpret_cast<const float4*>(L.src + (q << 2));
    }
    #pragma unroll
    for (int u = 0; u < NS; u++) {
        const int q = lane + 32 * (uS0 + u);
        if (q < S.n4)
            Sv[u] = *reinterpret_cast<const float4*>(S.src + (q << 2));
    }
    #pragma unroll
    for (int u = 0; u < NL; u++) {
        const int q = lane + 32 * (uL0 + u);
        if (q < L.n4) {
            const float4 v = Lv[u];
            *reinterpret_cast<float4*>(L.dst + (q << 2)) =
                make_float4(v.x - L.ai, v.y - L.ai, v.z - L.ai, v.w - L.ai);
        }
    }
    #pragma unroll
    for (int u = 0; u < NS; u++) {
        const int q = lane + 32 * (uS0 + u);
        if (q < S.n4) {
            const float4 v = Sv[u];
            *reinterpret_cast<float4*>(S.dst + (q << 2)) =
                make_float4(v.x - S.ai, v.y - S.ai, v.z - S.ai, v.w - S.ai);
        }
    }
}

__global__ __launch_bounds__(THREADS)
void relpos_kernel(const float* __restrict__ in, float* __restrict__ out) {
    // 4 shifted copies: sh[r*PITCH + m] = a[m + r]
    __shared__ float sh[4 * PITCH];

    const int b = blockIdx.y;
    const float* a = in + (size_t)b * N_ELEM;

    // Stage input + build shifted copies (one float4 per thread).
    {
        const float4 v = reinterpret_cast<const float4*>(a)[threadIdx.x];
        const int idx = threadIdx.x * 4;
        const float vv[4] = {v.x, v.y, v.z, v.w};
        #pragma unroll
        for (int e = 0; e < 4; e++) {
            const int x = idx + e;
            const float val = vv[e];
            #pragma unroll
            for (int r = 0; r < 4; r++) {
                const int m = x - r;
                if (m >= 0) sh[r * PITCH + m] = val;
            }
        }
    }
    __syncthreads();

    float* outb = out + (size_t)b * M_PAIRS;
    const int warp = threadIdx.x >> 5;
    const int lane = threadIdx.x & 31;

    #pragma unroll
    for (int sub = 0; sub < 2; sub++) {
        const int p = blockIdx.x * PAIRS_PER_BLOCK + warp + 8 * sub; // 0..511
        const int iS = 1022 - p;

        RowCtx L = row_setup(p, sh, outb, lane);
        RowCtx S;
        S.n4 = 0; S.ai = 0.f; S.src = sh; S.dst = outb;
        if (p < 511) S = row_setup(iS, sh, outb, lane);

        // Group 1: long batches 0..3, short batches 0..1  (6 live buffers)
        do_group<4, 2>(L, S, lane, 0, 0);
        // Group 2: long batches 4..7, short batches 2..3
        do_group<4, 2>(L, S, lane, 4, 2);
    }
}

extern "C" void kernel_launch(void* const* d_in, const int* in_sizes, int n_in,
                              void* d_out, int out_size) {
    const float* in = (const float*)d_in[0];
    float* out = (float*)d_out;
    const int B = in_sizes[0] / N_ELEM;               // 128

    dim3 grid(512 / PAIRS_PER_BLOCK, B);              // (32, 128)
    relpos_kernel<<<grid, THREADS>>>(in, out);
}